// round 1
// baseline (speedup 1.0000x reference)
#include <cuda_runtime.h>
#include <cuda_bf16.h>

// Problem constants
#define BB   4
#define NTOK 4096
#define PD   1024
#define DD   16
#define SS   64
#define NC   (NTOK / DD)          // 256 chunks per batch

// Scratch (device globals: allocation-free rule)
__device__ float g_P[(size_t)BB * NTOK * 2048];   // P = x@W_r + b_r   (128 MiB)
__device__ float g_Q[(size_t)BB * NTOK * 1024];   // Qg                (64 MiB)

// ---------------------------------------------------------------------------
// SGEMM: C[M,N] = A[M,K] @ B[K,N] + bias[N]   (all row-major, fp32)
// BM=BN=128, BK=16, 256 threads, 8x8 per-thread microtile.
// Assumes M%128==0, N%128==0, K%16==0 (true for both GEMMs here).
// ---------------------------------------------------------------------------
#define BM 128
#define BN 128
#define BK 16

__global__ __launch_bounds__(256, 2)
void sgemm_bias_kernel(const float* __restrict__ A, const float* __restrict__ B,
                       const float* __restrict__ bias, float* __restrict__ C,
                       int M, int N, int K)
{
    __shared__ float As[BK][BM];
    __shared__ float Bs[BK][BN];

    const int tid = threadIdx.x;
    const int bx = blockIdx.x;     // N tiles
    const int by = blockIdx.y;     // M tiles
    const int tx = tid & 15;       // 0..15
    const int ty = tid >> 4;       // 0..15

    const float* Ablk = A + (long)by * BM * K;
    const float* Bblk = B + bx * BN;

    float acc[8][8];
    #pragma unroll
    for (int i = 0; i < 8; i++)
        #pragma unroll
        for (int j = 0; j < 8; j++) acc[i][j] = 0.f;

    float regM[8], regN[8];

    for (int k0 = 0; k0 < K; k0 += BK) {
        // A tile: BM x BK, 512 float4 loads, store transposed
        #pragma unroll
        for (int r = 0; r < 2; r++) {
            int idx = tid + r * 256;           // 0..511
            int row = idx >> 2;                // 0..127
            int c4  = (idx & 3) * 4;           // 0,4,8,12
            float4 v = *(const float4*)(Ablk + (long)row * K + k0 + c4);
            As[c4 + 0][row] = v.x;
            As[c4 + 1][row] = v.y;
            As[c4 + 2][row] = v.z;
            As[c4 + 3][row] = v.w;
        }
        // B tile: BK x BN, 512 float4 loads
        #pragma unroll
        for (int r = 0; r < 2; r++) {
            int idx = tid + r * 256;
            int row = idx >> 5;                // 0..15
            int c4  = (idx & 31) * 4;          // 0..124
            *(float4*)(&Bs[row][c4]) =
                *(const float4*)(Bblk + (long)(k0 + row) * N + c4);
        }
        __syncthreads();

        #pragma unroll
        for (int k = 0; k < BK; k++) {
            #pragma unroll
            for (int i = 0; i < 8; i++) regM[i] = As[k][ty * 8 + i];
            #pragma unroll
            for (int j = 0; j < 8; j++) regN[j] = Bs[k][tx * 8 + j];
            #pragma unroll
            for (int i = 0; i < 8; i++)
                #pragma unroll
                for (int j = 0; j < 8; j++)
                    acc[i][j] += regM[i] * regN[j];
        }
        __syncthreads();
    }

    // Epilogue: add bias, vectorized stores
    #pragma unroll
    for (int i = 0; i < 8; i++) {
        long row = (long)by * BM + ty * 8 + i;
        #pragma unroll
        for (int j = 0; j < 8; j += 4) {
            int col = bx * BN + tx * 8 + j;
            float4 v;
            v.x = acc[i][j + 0] + bias[col + 0];
            v.y = acc[i][j + 1] + bias[col + 1];
            v.z = acc[i][j + 2] + bias[col + 2];
            v.w = acc[i][j + 3] + bias[col + 3];
            *(float4*)(C + row * N + col) = v;
        }
    }
}

// ---------------------------------------------------------------------------
// Middle kernel. Derivation collapses the reference's pad/gather/softmax/
// 3-matmul/gather pipeline to:
//   p[n, m, s]  = softmax_m( P[b, n, 0, m, s] )                (16-wide)
//   Qg[n, d, s] = sum_{m=0}^{d-1} p[n,m,s] * P1[(n+m+1)%N, d-1-m, s]
//   Qg = 0 when chunk==NC-1 and t+d >= 16   (the Q1 mask)
// Block = (s-group of 16, chunk, batch); 256 threads = 16 t x 16 s.
// P1 window of 30 tokens staged in shared (padded: conflict-free).
// ---------------------------------------------------------------------------
__global__ __launch_bounds__(256)
void middle_kernel(const float* __restrict__ P, float* __restrict__ Q)
{
    __shared__ float sR[30][16][17];   // [token offset][d][s-local], pad 17

    const int sg = blockIdx.x;         // 0..3  (s group)
    const int c  = blockIdx.y;         // 0..255 chunk
    const int b  = blockIdx.z;         // 0..3
    const int tid = threadIdx.x;
    const int sl = tid & 15;           // s local 0..15
    const int t  = tid >> 4;           // token-in-chunk 0..15

    const long Pbase = (long)b * NTOK * 2048;

    // Stage P1 for tokens (c*16 + u + 1) % NTOK, u in [0,30)
    for (int i = tid; i < 30 * 16 * 16; i += 256) {
        int s16 = i & 15;
        int d   = (i >> 4) & 15;
        int u   = i >> 8;
        int tokn = c * DD + u + 1;
        if (tokn >= NTOK) tokn -= NTOK;
        sR[u][d][s16] =
            P[Pbase + (long)tokn * 2048 + 1024 + d * 64 + sg * 16 + s16];
    }
    __syncthreads();

    const int n = c * DD + t;
    const float* p0 = P + Pbase + (long)n * 2048 + sg * 16 + sl;  // stride 64 per d

    // softmax over 16 logits (the -10000 pad entries vanish: exp underflows to 0)
    float v[16];
    float mx = -1e30f;
    #pragma unroll
    for (int d = 0; d < 16; d++) { v[d] = p0[d * 64]; mx = fmaxf(mx, v[d]); }
    float sum = 0.f;
    #pragma unroll
    for (int d = 0; d < 16; d++) { v[d] = __expf(v[d] - mx); sum += v[d]; }
    const float inv = 1.f / sum;
    #pragma unroll
    for (int d = 0; d < 16; d++) v[d] *= inv;

    float* qout = Q + ((long)b * NTOK + n) * 1024 + sg * 16 + sl;
    const bool lastc = (c == NC - 1);

    #pragma unroll
    for (int d = 0; d < 16; d++) {
        float acc = 0.f;
        #pragma unroll
        for (int m = 0; m < d; m++)
            acc += v[m] * sR[t + m][d - 1 - m][sl];
        if (lastc && (t + d >= DD)) acc = 0.f;
        qout[d * 64] = acc;
    }
}

// ---------------------------------------------------------------------------
extern "C" void kernel_launch(void* const* d_in, const int* in_sizes, int n_in,
                              void* d_out, int out_size)
{
    const float* x  = (const float*)d_in[0];   // [4,4096,1024]
    const float* Wr = (const float*)d_in[1];   // [1024,2048]
    const float* br = (const float*)d_in[2];   // [2048]
    const float* Ww = (const float*)d_in[3];   // [1024,1024]
    const float* bw = (const float*)d_in[4];   // [1024]
    float* out = (float*)d_out;                // [4,4096,1024]

    float *P, *Q;
    cudaGetSymbolAddress((void**)&P, g_P);
    cudaGetSymbolAddress((void**)&Q, g_Q);

    const int M = BB * NTOK;   // 16384

    // GEMM1: P = x @ W_r + b_r   [16384,1024]x[1024,2048]
    {
        dim3 grid(2048 / BN, M / BM);
        sgemm_bias_kernel<<<grid, 256>>>(x, Wr, br, P, M, 2048, PD);
    }
    // Middle: softmax + triangular conv -> Qg
    {
        dim3 grid(4, NC, BB);
        middle_kernel<<<grid, 256>>>(P, Q);
    }
    // GEMM2: out = Qg @ W_w + b_w   [16384,1024]x[1024,1024]
    {
        dim3 grid(1024 / BN, M / BM);
        sgemm_bias_kernel<<<grid, 256>>>(Q, Ww, bw, out, M, 1024, PD);
    }
}

// round 4
// speedup vs baseline: 2.4458x; 2.4458x over previous
#include <cuda_runtime.h>
#include <cuda_bf16.h>
#include <cstdint>

// Problem constants
#define BB   4
#define NTOK 4096
#define PD   1024
#define DD   16
#define NC   (NTOK / DD)
#define GK   1024                 // K of both GEMMs
#define GM   (BB * NTOK)          // 16384 rows

// ---------------------------------------------------------------------------
// Scratch (device globals: allocation-free rule)
// ---------------------------------------------------------------------------
__device__ float g_P[(size_t)GM * 2048];              // P  (128 MiB)
__device__ __nv_bfloat16 g_Ah[(size_t)GM * GK];       // x hi   (32 MiB)
__device__ __nv_bfloat16 g_Al[(size_t)GM * GK];       // x lo
__device__ __nv_bfloat16 g_Qh[(size_t)GM * 1024];     // Q hi
__device__ __nv_bfloat16 g_Ql[(size_t)GM * 1024];     // Q lo
__device__ __nv_bfloat16 g_B1h[2048 * GK];            // W_r^T hi [N][K]
__device__ __nv_bfloat16 g_B1l[2048 * GK];
__device__ __nv_bfloat16 g_B2h[1024 * GK];            // W_w^T hi [N][K]
__device__ __nv_bfloat16 g_B2l[1024 * GK];

// ---------------------------------------------------------------------------
// PTX helpers (plain sm_103-legal only: cp.async / ldmatrix / mma.sync)
// ---------------------------------------------------------------------------
__device__ __forceinline__ uint32_t smem_to_u32(const void* p) {
    uint32_t a;
    asm("{ .reg .u64 t; cvta.to.shared.u64 t, %1; cvt.u32.u64 %0, t; }"
        : "=r"(a) : "l"(p));
    return a;
}

#define CP_ASYNC16(saddr, gptr) \
    asm volatile("cp.async.cg.shared.global [%0], [%1], 16;" \
                 :: "r"(saddr), "l"(gptr))
#define CP_COMMIT() asm volatile("cp.async.commit_group;" ::: "memory")
#define CP_WAIT(n)  asm volatile("cp.async.wait_group %0;" :: "n"(n) : "memory")

__device__ __forceinline__ void ldsm_x4(uint32_t (&r)[4], uint32_t addr) {
    asm volatile("ldmatrix.sync.aligned.m8n8.x4.shared.b16 {%0,%1,%2,%3}, [%4];"
                 : "=r"(r[0]), "=r"(r[1]), "=r"(r[2]), "=r"(r[3]) : "r"(addr));
}

__device__ __forceinline__ void mma_bf16(float (&d)[4], const uint32_t (&a)[4],
                                         uint32_t b0, uint32_t b1) {
    asm volatile(
        "mma.sync.aligned.m16n8k16.row.col.f32.bf16.bf16.f32 "
        "{%0,%1,%2,%3}, {%4,%5,%6,%7}, {%8,%9}, {%0,%1,%2,%3};"
        : "+f"(d[0]), "+f"(d[1]), "+f"(d[2]), "+f"(d[3])
        : "r"(a[0]), "r"(a[1]), "r"(a[2]), "r"(a[3]), "r"(b0), "r"(b1));
}

// Swizzled byte offset inside a [128 rows][64 B] tile.
// 8 consecutive rows at fixed kbyte map to 8 distinct 16B slots mod 128B.
__device__ __forceinline__ uint32_t tile_off(int row, int kbyte) {
    return (uint32_t)(row * 64 + (kbyte ^ (((row >> 1) & 3) << 4)));
}

// ---------------------------------------------------------------------------
// Prep kernels
// ---------------------------------------------------------------------------
__global__ void split_x_kernel(const float* __restrict__ X,
                               __nv_bfloat16* __restrict__ H,
                               __nv_bfloat16* __restrict__ L)
{
    size_t i = (size_t)blockIdx.x * blockDim.x + threadIdx.x;   // float4 idx
    float4 v = ((const float4*)X)[i];
    __nv_bfloat16 h[4], l[4];
    float f[4] = {v.x, v.y, v.z, v.w};
    #pragma unroll
    for (int q = 0; q < 4; q++) {
        h[q] = __float2bfloat16(f[q]);
        l[q] = __float2bfloat16(f[q] - __bfloat162float(h[q]));
    }
    *(uint64_t*)(H + i * 4) = *(uint64_t*)h;
    *(uint64_t*)(L + i * 4) = *(uint64_t*)l;
}

__global__ void transpose_split_kernel(const float* __restrict__ W,
                                       __nv_bfloat16* __restrict__ Bh,
                                       __nv_bfloat16* __restrict__ Bl,
                                       int K, int N)
{
    __shared__ float t[32][33];
    const int n0 = blockIdx.x * 32, k0 = blockIdx.y * 32;
    const int tx = threadIdx.x, ty = threadIdx.y;
    #pragma unroll
    for (int i = 0; i < 32; i += 8)
        t[ty + i][tx] = W[(size_t)(k0 + ty + i) * N + n0 + tx];
    __syncthreads();
    #pragma unroll
    for (int i = 0; i < 32; i += 8) {
        float v = t[tx][ty + i];
        __nv_bfloat16 h = __float2bfloat16(v);
        __nv_bfloat16 l = __float2bfloat16(v - __bfloat162float(h));
        size_t o = (size_t)(n0 + ty + i) * K + (k0 + tx);
        Bh[o] = h; Bl[o] = l;
    }
}

// ---------------------------------------------------------------------------
// bf16-split GEMM via mma.sync:  C[M,N] = A @ B^T + bias
//   A: Ah/Al [M][K] bf16 row-major;  B: Bh/Bl [N][K] bf16 row-major
//   3 passes: Ah*Bh + Ah*Bl + Al*Bh (fp32 accum)
// Tile 128x128xBK32, 3-stage cp.async pipeline, 256 threads (2x4 warps).
// ---------------------------------------------------------------------------
#define STAGE_BYTES 32768            // 4 mats x (128 x 32 bf16 = 8 KB)
#define OFF_AH 0
#define OFF_AL 8192
#define OFF_BH 16384
#define OFF_BL 24576
#define NSTAGE 3
#define GEMM_SMEM (NSTAGE * STAGE_BYTES)
#define NCHUNK (GK / 32)

__device__ __forceinline__ void issue_stage(uint32_t sbase,
    const __nv_bfloat16* __restrict__ Ah, const __nv_bfloat16* __restrict__ Al,
    const __nv_bfloat16* __restrict__ Bh, const __nv_bfloat16* __restrict__ Bl,
    int k0, int tid)
{
    #pragma unroll
    for (int h = 0; h < 2; h++) {
        int idx = tid + h * 256;            // 0..511
        int row = idx >> 2;                 // 0..127
        int kc  = idx & 3;                  // 16B chunk in row
        uint32_t off = tile_off(row, kc * 16);
        size_t g = (size_t)row * GK + k0 + kc * 8;
        CP_ASYNC16(sbase + OFF_AH + off, Ah + g);
        CP_ASYNC16(sbase + OFF_AL + off, Al + g);
        CP_ASYNC16(sbase + OFF_BH + off, Bh + g);
        CP_ASYNC16(sbase + OFF_BL + off, Bl + g);
    }
}

__global__ __launch_bounds__(256)
void gemm_mma_kernel(const __nv_bfloat16* __restrict__ Ah,
                     const __nv_bfloat16* __restrict__ Al,
                     const __nv_bfloat16* __restrict__ Bh,
                     const __nv_bfloat16* __restrict__ Bl,
                     const float* __restrict__ bias,
                     float* __restrict__ C, int N)
{
    extern __shared__ char smem[];
    const uint32_t sbase = smem_to_u32(smem);
    const int tid  = threadIdx.x;
    const int lane = tid & 31;
    const int wid  = tid >> 5;
    const int wm   = wid & 1;           // 0..1  (64-row half)
    const int wn   = wid >> 1;          // 0..3  (32-col quarter)
    const int m0 = blockIdx.y * 128;
    const int n0 = blockIdx.x * 128;

    const __nv_bfloat16* Ahb = Ah + (size_t)m0 * GK;
    const __nv_bfloat16* Alb = Al + (size_t)m0 * GK;
    const __nv_bfloat16* Bhb = Bh + (size_t)n0 * GK;
    const __nv_bfloat16* Blb = Bl + (size_t)n0 * GK;

    float acc[4][4][4];
    #pragma unroll
    for (int i = 0; i < 4; i++)
        #pragma unroll
        for (int j = 0; j < 4; j++)
            #pragma unroll
            for (int q = 0; q < 4; q++) acc[i][j][q] = 0.f;

    // prologue: stages 0,1
    issue_stage(sbase + 0 * STAGE_BYTES, Ahb, Alb, Bhb, Blb, 0, tid);
    CP_COMMIT();
    issue_stage(sbase + 1 * STAGE_BYTES, Ahb, Alb, Bhb, Blb, 32, tid);
    CP_COMMIT();

    // ldmatrix lane addressing pieces
    const int lrow = lane & 15;
    const int lcol = (lane >> 4) * 16;

    for (int c = 0; c < NCHUNK; c++) {
        if (c + 2 < NCHUNK) CP_WAIT(1); else CP_WAIT(0);
        __syncthreads();

        if (c + 2 < NCHUNK) {
            issue_stage(sbase + ((c + 2) % NSTAGE) * STAGE_BYTES,
                        Ahb, Alb, Bhb, Blb, (c + 2) * 32, tid);
            CP_COMMIT();
        }

        const uint32_t sb = sbase + (c % NSTAGE) * STAGE_BYTES;

        #pragma unroll
        for (int ks = 0; ks < 2; ks++) {
            const int kb = ks * 32 + lcol;
            uint32_t ah[4][4], al[4][4];
            #pragma unroll
            for (int mt = 0; mt < 4; mt++) {
                uint32_t o = tile_off(wm * 64 + mt * 16 + lrow, kb);
                ldsm_x4(ah[mt], sb + OFF_AH + o);
                ldsm_x4(al[mt], sb + OFF_AL + o);
            }
            uint32_t bh[2][4], bl[2][4];
            #pragma unroll
            for (int ng = 0; ng < 2; ng++) {
                uint32_t o = tile_off(wn * 32 + ng * 16 + lrow, kb);
                ldsm_x4(bh[ng], sb + OFF_BH + o);
                ldsm_x4(bl[ng], sb + OFF_BL + o);
            }
            #pragma unroll
            for (int mt = 0; mt < 4; mt++)
                #pragma unroll
                for (int nt = 0; nt < 4; nt++)
                    mma_bf16(acc[mt][nt], ah[mt],
                             bh[nt >> 1][nt & 1], bh[nt >> 1][(nt & 1) + 2]);
            #pragma unroll
            for (int mt = 0; mt < 4; mt++)
                #pragma unroll
                for (int nt = 0; nt < 4; nt++)
                    mma_bf16(acc[mt][nt], ah[mt],
                             bl[nt >> 1][nt & 1], bl[nt >> 1][(nt & 1) + 2]);
            #pragma unroll
            for (int mt = 0; mt < 4; mt++)
                #pragma unroll
                for (int nt = 0; nt < 4; nt++)
                    mma_bf16(acc[mt][nt], al[mt],
                             bh[nt >> 1][nt & 1], bh[nt >> 1][(nt & 1) + 2]);
        }
    }

    // epilogue
    float* Cblk = C + (size_t)m0 * N + n0;
    #pragma unroll
    for (int mt = 0; mt < 4; mt++) {
        #pragma unroll
        for (int nt = 0; nt < 4; nt++) {
            int r  = wm * 64 + mt * 16 + (lane >> 2);
            int cc = wn * 32 + nt * 8 + (lane & 3) * 2;
            float b0 = __ldg(&bias[n0 + cc]);
            float b1 = __ldg(&bias[n0 + cc + 1]);
            float2 v0 = {acc[mt][nt][0] + b0, acc[mt][nt][1] + b1};
            float2 v1 = {acc[mt][nt][2] + b0, acc[mt][nt][3] + b1};
            *(float2*)(Cblk + (size_t)r * N + cc) = v0;
            *(float2*)(Cblk + (size_t)(r + 8) * N + cc) = v1;
        }
    }
}

// ---------------------------------------------------------------------------
// Middle kernel (math verified in R1, rel_err 8.6e-7); now emits Q split into
// bf16 hi/lo so GEMM2 consumes it directly.
//   p[n,m,s]  = softmax_m( P[b,n,0,m,s] )
//   Qg[n,d,s] = sum_{m<d} p[n,m,s] * P1[(n+m+1)%N, d-1-m, s];  masked last chunk
// ---------------------------------------------------------------------------
__global__ __launch_bounds__(256)
void middle_kernel(const float* __restrict__ P,
                   __nv_bfloat16* __restrict__ Qh,
                   __nv_bfloat16* __restrict__ Ql)
{
    __shared__ float sR[30][16][17];

    const int sg = blockIdx.x;
    const int c  = blockIdx.y;
    const int b  = blockIdx.z;
    const int tid = threadIdx.x;
    const int sl = tid & 15;
    const int t  = tid >> 4;

    const long Pbase = (long)b * NTOK * 2048;

    for (int i = tid; i < 30 * 16 * 16; i += 256) {
        int s16 = i & 15;
        int d   = (i >> 4) & 15;
        int u   = i >> 8;
        int tokn = c * DD + u + 1;
        if (tokn >= NTOK) tokn -= NTOK;
        sR[u][d][s16] =
            P[Pbase + (long)tokn * 2048 + 1024 + d * 64 + sg * 16 + s16];
    }
    __syncthreads();

    const int n = c * DD + t;
    const float* p0 = P + Pbase + (long)n * 2048 + sg * 16 + sl;

    float v[16];
    float mx = -1e30f;
    #pragma unroll
    for (int d = 0; d < 16; d++) { v[d] = p0[d * 64]; mx = fmaxf(mx, v[d]); }
    float sum = 0.f;
    #pragma unroll
    for (int d = 0; d < 16; d++) { v[d] = __expf(v[d] - mx); sum += v[d]; }
    const float inv = 1.f / sum;
    #pragma unroll
    for (int d = 0; d < 16; d++) v[d] *= inv;

    const size_t qbase = ((size_t)b * NTOK + n) * 1024 + sg * 16 + sl;
    const bool lastc = (c == NC - 1);

    #pragma unroll
    for (int d = 0; d < 16; d++) {
        float acc = 0.f;
        #pragma unroll
        for (int m = 0; m < d; m++)
            acc += v[m] * sR[t + m][d - 1 - m][sl];
        if (lastc && (t + d >= DD)) acc = 0.f;
        __nv_bfloat16 h = __float2bfloat16(acc);
        __nv_bfloat16 l = __float2bfloat16(acc - __bfloat162float(h));
        Qh[qbase + d * 64] = h;
        Ql[qbase + d * 64] = l;
    }
}

// ---------------------------------------------------------------------------
extern "C" void kernel_launch(void* const* d_in, const int* in_sizes, int n_in,
                              void* d_out, int out_size)
{
    const float* x  = (const float*)d_in[0];   // [4,4096,1024]
    const float* Wr = (const float*)d_in[1];   // [1024,2048]
    const float* br = (const float*)d_in[2];   // [2048]
    const float* Ww = (const float*)d_in[3];   // [1024,1024]
    const float* bw = (const float*)d_in[4];   // [1024]
    float* out = (float*)d_out;                // [4,4096,1024]

    float* P;
    __nv_bfloat16 *Ah, *Al, *Qh, *Ql, *B1h, *B1l, *B2h, *B2l;
    cudaGetSymbolAddress((void**)&P,   g_P);
    cudaGetSymbolAddress((void**)&Ah,  g_Ah);
    cudaGetSymbolAddress((void**)&Al,  g_Al);
    cudaGetSymbolAddress((void**)&Qh,  g_Qh);
    cudaGetSymbolAddress((void**)&Ql,  g_Ql);
    cudaGetSymbolAddress((void**)&B1h, g_B1h);
    cudaGetSymbolAddress((void**)&B1l, g_B1l);
    cudaGetSymbolAddress((void**)&B2h, g_B2h);
    cudaGetSymbolAddress((void**)&B2l, g_B2l);

    cudaFuncSetAttribute(gemm_mma_kernel,
                         cudaFuncAttributeMaxDynamicSharedMemorySize, GEMM_SMEM);

    // Prep: split activations + weights
    split_x_kernel<<<(GM * GK / 4) / 256, 256>>>(x, Ah, Al);
    {
        dim3 blk(32, 8);
        transpose_split_kernel<<<dim3(2048 / 32, 1024 / 32), blk>>>(Wr, B1h, B1l, GK, 2048);
        transpose_split_kernel<<<dim3(1024 / 32, 1024 / 32), blk>>>(Ww, B2h, B2l, GK, 1024);
    }
    // GEMM1: P = x @ W_r + b_r   [16384,1024] x [1024,2048]
    {
        dim3 grid(2048 / 128, GM / 128);
        gemm_mma_kernel<<<grid, 256, GEMM_SMEM>>>(Ah, Al, B1h, B1l, br, P, 2048);
    }
    // Middle: softmax + triangular conv -> Qh/Ql (bf16 split)
    {
        dim3 grid(4, NC, BB);
        middle_kernel<<<grid, 256>>>(P, Qh, Ql);
    }
    // GEMM2: out = Q @ W_w + b_w   [16384,1024] x [1024,1024]
    {
        dim3 grid(1024 / 128, GM / 128);
        gemm_mma_kernel<<<grid, 256, GEMM_SMEM>>>(Qh, Ql, B2h, B2l, bw, out, 1024);
    }
}